// round 2
// baseline (speedup 1.0000x reference)
#include <cuda_runtime.h>
#include <math.h>

// ---------------------------------------------------------------------------
// Static device scratch (no runtime allocation allowed).
// Two ping-pong buffers sized for the largest tensor: 4*64*416*416 floats.
// ---------------------------------------------------------------------------
#define BIG_ELEMS 44302336   // 4*64*416*416  (also >= 4*128*208*208 = 22151168)
__device__ float g_buf0[BIG_ELEMS];
__device__ float g_buf1[BIG_ELEMS];
__device__ float g_t[346112];        // 4*128*26*26
__device__ float g_w16[16];
__device__ float g_bnsc[128];
__device__ float g_bnsh[128];

// ---------------------------------------------------------------------------
// Direct 3x3 conv, pad=1, stride=1, NCHW.
// Block = 256 threads -> 32x32 output tile, 2x2 outputs per thread,
// COPB output channels per block.
// Epilogue: act 0=none, 1=relu, 2=sigmoid; optional per-channel scale/shift
// (applied AFTER relu, matching reference relu->bn ordering).
// ---------------------------------------------------------------------------
template<int COPB>
__global__ void conv3x3_k(const float* __restrict__ in, const float* __restrict__ wt,
                          const float* __restrict__ bias, float* __restrict__ out,
                          int N, int Cin, int Co, int H, int W,
                          const float* __restrict__ bnsc, const float* __restrict__ bnsh,
                          int act)
{
    __shared__ float s_in[34 * 34];
    __shared__ float s_w[COPB * 9];

    const int tx = threadIdx.x & 15;        // 0..15
    const int ty = threadIdx.x >> 4;        // 0..15
    const int tile_x = blockIdx.x * 32;
    const int tile_y = blockIdx.y * 32;
    const int co_blocks = (Co + COPB - 1) / COPB;
    const int n   = blockIdx.z / co_blocks;
    const int co0 = (blockIdx.z % co_blocks) * COPB;
    const int ox = tile_x + 2 * tx;         // this thread's 2x2 patch origin
    const int oy = tile_y + 2 * ty;

    float acc[COPB][4];
#pragma unroll
    for (int j = 0; j < COPB; j++)
#pragma unroll
        for (int p = 0; p < 4; p++) acc[j][p] = 0.f;

    const float* inN = in + (size_t)n * Cin * H * W;

    for (int ci = 0; ci < Cin; ci++) {
        const float* inC = inN + (size_t)ci * H * W;
        // cooperative load of 34x34 halo tile (zero-padded), 1156 elems
        for (int idx = threadIdx.x; idx < 1156; idx += 256) {
            int iy = tile_y - 1 + idx / 34;
            int ix = tile_x - 1 + idx % 34;
            float v = 0.f;
            if (iy >= 0 && iy < H && ix >= 0 && ix < W) v = __ldg(&inC[iy * W + ix]);
            s_in[idx] = v;
        }
        if (threadIdx.x < COPB * 9) {
            int j = threadIdx.x / 9;
            int k = threadIdx.x - j * 9;
            int co = co0 + j;
            s_w[threadIdx.x] = (co < Co) ? __ldg(&wt[((size_t)co * Cin + ci) * 9 + k]) : 0.f;
        }
        __syncthreads();

        // 4x4 input patch for this thread's 2x2 outputs
        float r[4][4];
#pragma unroll
        for (int dy = 0; dy < 4; dy++)
#pragma unroll
            for (int dx = 0; dx < 4; dx++)
                r[dy][dx] = s_in[(2 * ty + dy) * 34 + 2 * tx + dx];

#pragma unroll
        for (int j = 0; j < COPB; j++) {
#pragma unroll
            for (int ky = 0; ky < 3; ky++)
#pragma unroll
                for (int kx = 0; kx < 3; kx++) {
                    float w = s_w[j * 9 + ky * 3 + kx];
                    acc[j][0] = fmaf(r[ky    ][kx    ], w, acc[j][0]);
                    acc[j][1] = fmaf(r[ky    ][kx + 1], w, acc[j][1]);
                    acc[j][2] = fmaf(r[ky + 1][kx    ], w, acc[j][2]);
                    acc[j][3] = fmaf(r[ky + 1][kx + 1], w, acc[j][3]);
                }
        }
        __syncthreads();
    }

#pragma unroll
    for (int j = 0; j < COPB; j++) {
        int co = co0 + j;
        if (co < Co) {
            float bv = __ldg(&bias[co]);
            float sc = 1.f, sh = 0.f;
            if (bnsc) { sc = __ldg(&bnsc[co]); sh = __ldg(&bnsh[co]); }
            float* outC = out + (((size_t)n * Co + co) * H) * W;
#pragma unroll
            for (int p = 0; p < 4; p++) {
                int yy = oy + (p >> 1);
                int xx = ox + (p & 1);
                if (yy < H && xx < W) {
                    float v = acc[j][p] + bv;
                    if (act == 1) v = fmaxf(v, 0.f);
                    v = v * sc + sh;
                    if (act == 2) v = 1.f / (1.f + expf(-v));
                    outC[(size_t)yy * W + xx] = v;
                }
            }
        }
    }
}

// ---------------------------------------------------------------------------
// 2x2 max pool, stride 2
// ---------------------------------------------------------------------------
__global__ void maxpool_k(const float* __restrict__ in, float* __restrict__ out,
                          int NC, int H, int W)
{
    int Ho = H >> 1, Wo = W >> 1;
    long total = (long)NC * Ho * Wo;
    for (long i = blockIdx.x * (long)blockDim.x + threadIdx.x; i < total;
         i += (long)gridDim.x * blockDim.x) {
        int xo = (int)(i % Wo);
        int yo = (int)((i / Wo) % Ho);
        long nc = i / ((long)Wo * Ho);
        const float* p = in + (size_t)nc * H * W + (size_t)(2 * yo) * W + 2 * xo;
        out[i] = fmaxf(fmaxf(p[0], p[1]), fmaxf(p[W], p[W + 1]));
    }
}

// ---------------------------------------------------------------------------
// Bilinear 2x upsample, align_corners=True
// ---------------------------------------------------------------------------
__global__ void up2_k(const float* __restrict__ in, float* __restrict__ out,
                      int NC, int H, int W)
{
    int Ho = 2 * H, Wo = 2 * W;
    float sy = (float)(H - 1) / (float)(Ho - 1);
    float sx = (float)(W - 1) / (float)(Wo - 1);
    long total = (long)NC * Ho * Wo;
    for (long i = blockIdx.x * (long)blockDim.x + threadIdx.x; i < total;
         i += (long)gridDim.x * blockDim.x) {
        int xo = (int)(i % Wo);
        int yo = (int)((i / Wo) % Ho);
        long nc = i / ((long)Wo * Ho);
        float ys = yo * sy, xs = xo * sx;
        int y0 = (int)floorf(ys), x0 = (int)floorf(xs);
        int y1 = min(y0 + 1, H - 1), x1 = min(x0 + 1, W - 1);
        float wy = ys - (float)y0, wx = xs - (float)x0;
        const float* p = in + (size_t)nc * H * W;
        float a = p[y0 * W + x0] * (1.f - wy) + p[y1 * W + x0] * wy;
        float b = p[y0 * W + x1] * (1.f - wy) + p[y1 * W + x1] * wy;
        out[i] = a * (1.f - wx) + b * wx;
    }
}

// ---------------------------------------------------------------------------
// Block attention, collapsed:
//   t[b,c,h,w]  = sum_{k,l} x[b,c, k*26+h, l*26+w]            (h,w in [0,26))
//   w16[m,n]    = (1/676) * sum_{b,c,h,w} x_block(m,n)[...] * t[...]
//   y = x * w16[block(i), block(j)]     (in place)
// ---------------------------------------------------------------------------
__global__ void attn_t_k(const float* __restrict__ x, float* __restrict__ t)
{
    const int total = 4 * 128 * 26 * 26;  // 346112
    for (int i = blockIdx.x * blockDim.x + threadIdx.x; i < total;
         i += gridDim.x * blockDim.x) {
        int w  = i % 26;
        int h  = (i / 26) % 26;
        int bc = i / 676;
        const float* p = x + (size_t)bc * 104 * 104;
        float s = 0.f;
#pragma unroll
        for (int k = 0; k < 4; k++)
#pragma unroll
            for (int l = 0; l < 4; l++)
                s += p[(k * 26 + h) * 104 + l * 26 + w];
        t[i] = s;
    }
}

__global__ void attn_w_k(const float* __restrict__ x, const float* __restrict__ t,
                         float* __restrict__ w16)
{
    const int mn = blockIdx.x;            // 16 blocks, one per weight
    const int m = mn >> 2, nn = mn & 3;
    const int total = 4 * 128 * 26 * 26;
    float s = 0.f;
    for (int i = threadIdx.x; i < total; i += blockDim.x) {
        int w  = i % 26;
        int h  = (i / 26) % 26;
        int bc = i / 676;
        s += x[(size_t)bc * 104 * 104 + (m * 26 + h) * 104 + nn * 26 + w] * t[i];
    }
    __shared__ float red[1024];
    red[threadIdx.x] = s;
    __syncthreads();
    for (int st = blockDim.x >> 1; st > 0; st >>= 1) {
        if (threadIdx.x < st) red[threadIdx.x] += red[threadIdx.x + st];
        __syncthreads();
    }
    if (threadIdx.x == 0) w16[mn] = red[0] * (1.f / 676.f);
}

__global__ void attn_scale_k(float* __restrict__ x, const float* __restrict__ w16)
{
    const long total = 4L * 128 * 104 * 104;  // 5537792
    for (long i = blockIdx.x * (long)blockDim.x + threadIdx.x; i < total;
         i += (long)gridDim.x * blockDim.x) {
        int j  = (int)(i % 104);
        int ii = (int)((i / 104) % 104);
        x[i] *= w16[(ii / 26) * 4 + (j / 26)];
    }
}

// ---------------------------------------------------------------------------
// Fold BN (inference) into per-channel scale/shift.
// ---------------------------------------------------------------------------
__global__ void bn_prep_k(const float* __restrict__ g, const float* __restrict__ b,
                          const float* __restrict__ m, const float* __restrict__ v,
                          float* __restrict__ sc, float* __restrict__ sh, int C)
{
    int c = blockIdx.x * blockDim.x + threadIdx.x;
    if (c < C) {
        float s = g[c] / sqrtf(v[c] + 1e-5f);
        sc[c] = s;
        sh[c] = b[c] - m[c] * s;
    }
}

// ---------------------------------------------------------------------------
// Host orchestration (graph-capturable: kernel launches only, default stream)
// ---------------------------------------------------------------------------
static inline dim3 conv_grid(int W, int H, int N, int Co, int copb)
{
    return dim3((W + 31) / 32, (H + 31) / 32, N * ((Co + copb - 1) / copb));
}

extern "C" void kernel_launch(void* const* d_in, const int* in_sizes, int n_in,
                              void* d_out, int out_size)
{
    (void)in_sizes; (void)n_in; (void)out_size;
    const float* x    = (const float*)d_in[0];
    const float* w1   = (const float*)d_in[1];
    const float* b1   = (const float*)d_in[2];
    const float* w2   = (const float*)d_in[3];
    const float* b2   = (const float*)d_in[4];
    const float* w3   = (const float*)d_in[5];
    const float* b3   = (const float*)d_in[6];
    const float* w4   = (const float*)d_in[7];
    const float* b4   = (const float*)d_in[8];
    const float* dw1  = (const float*)d_in[9];
    const float* db1  = (const float*)d_in[10];
    const float* dw2  = (const float*)d_in[11];
    const float* db2  = (const float*)d_in[12];
    const float* dw3  = (const float*)d_in[13];
    const float* db3  = (const float*)d_in[14];
    const float* dw4  = (const float*)d_in[15];
    const float* db4  = (const float*)d_in[16];
    const float* dw5  = (const float*)d_in[17];
    const float* db5  = (const float*)d_in[18];
    const float* bn2g = (const float*)d_in[19];
    const float* bn2b = (const float*)d_in[20];
    const float* bn2m = (const float*)d_in[21];
    const float* bn2v = (const float*)d_in[22];
    const float* bn4g = (const float*)d_in[23];
    const float* bn4b = (const float*)d_in[24];
    const float* bn4m = (const float*)d_in[25];
    const float* bn4v = (const float*)d_in[26];
    float* out = (float*)d_out;

    float *buf0, *buf1, *tb, *w16, *bnsc, *bnsh;
    cudaGetSymbolAddress((void**)&buf0, g_buf0);
    cudaGetSymbolAddress((void**)&buf1, g_buf1);
    cudaGetSymbolAddress((void**)&tb,   g_t);
    cudaGetSymbolAddress((void**)&w16,  g_w16);
    cudaGetSymbolAddress((void**)&bnsc, g_bnsc);
    cudaGetSymbolAddress((void**)&bnsh, g_bnsh);

    // Encoder
    conv3x3_k<8><<<conv_grid(416, 416, 4, 64, 8), 256>>>(x,    w1, b1, buf0, 4, 3,   64, 416, 416, nullptr, nullptr, 1);
    conv3x3_k<8><<<conv_grid(416, 416, 4, 64, 8), 256>>>(buf0, w2, b2, buf1, 4, 64,  64, 416, 416, nullptr, nullptr, 1);
    maxpool_k<<<4096, 256>>>(buf1, buf0, 4 * 64, 416, 416);
    conv3x3_k<8><<<conv_grid(208, 208, 4, 128, 8), 256>>>(buf0, w3, b3, buf1, 4, 64,  128, 208, 208, nullptr, nullptr, 1);
    conv3x3_k<8><<<conv_grid(208, 208, 4, 128, 8), 256>>>(buf1, w4, b4, buf0, 4, 128, 128, 208, 208, nullptr, nullptr, 1);
    maxpool_k<<<2048, 256>>>(buf0, buf1, 4 * 128, 208, 208);

    // Block attention x2 (in-place on buf1)
    attn_t_k<<<1352, 256>>>(buf1, tb);
    attn_w_k<<<16, 1024>>>(buf1, tb, w16);
    attn_scale_k<<<2048, 256>>>(buf1, w16);
    attn_t_k<<<1352, 256>>>(buf1, tb);
    attn_w_k<<<16, 1024>>>(buf1, tb, w16);
    attn_scale_k<<<2048, 256>>>(buf1, w16);

    // Decoder
    conv3x3_k<8><<<conv_grid(104, 104, 4, 128, 8), 256>>>(buf1, dw1, db1, buf0, 4, 128, 128, 104, 104, nullptr, nullptr, 1);
    bn_prep_k<<<1, 128>>>(bn2g, bn2b, bn2m, bn2v, bnsc, bnsh, 128);
    conv3x3_k<8><<<conv_grid(104, 104, 4, 128, 8), 256>>>(buf0, dw2, db2, buf1, 4, 128, 128, 104, 104, bnsc, bnsh, 1);
    up2_k<<<2048, 256>>>(buf1, buf0, 4 * 128, 104, 104);
    conv3x3_k<8><<<conv_grid(208, 208, 4, 64, 8), 256>>>(buf0, dw3, db3, buf1, 4, 128, 64, 208, 208, nullptr, nullptr, 1);
    bn_prep_k<<<1, 64>>>(bn4g, bn4b, bn4m, bn4v, bnsc, bnsh, 64);
    conv3x3_k<8><<<conv_grid(208, 208, 4, 64, 8), 256>>>(buf1, dw4, db4, buf0, 4, 64, 64, 208, 208, bnsc, bnsh, 1);
    up2_k<<<4096, 256>>>(buf0, buf1, 4 * 64, 208, 208);
    conv3x3_k<2><<<conv_grid(416, 416, 4, 2, 2), 256>>>(buf1, dw5, db5, out, 4, 64, 2, 416, 416, nullptr, nullptr, 2);
}

// round 4
// speedup vs baseline: 2.0047x; 2.0047x over previous
#include <cuda_runtime.h>
#include <stdint.h>
#include <math.h>

// ---------------------------------------------------------------------------
// Static device scratch (no runtime allocation allowed).
// ---------------------------------------------------------------------------
#define BIG_ELEMS 44302336   // 4*64*416*416  (also >= 4*128*208*208)
__device__ float g_buf0[BIG_ELEMS];
__device__ float g_buf1[BIG_ELEMS];
__device__ float g_t[346112];        // 4*128*26*26
__device__ float g_w16[16];
__device__ float g_bnsc[128];
__device__ float g_bnsh[128];

// ---------------------------------------------------------------------------
// f32x2 packed-math helpers (Blackwell sm_100a packed fp32 pipe)
// ---------------------------------------------------------------------------
typedef unsigned long long ull;

__device__ __forceinline__ ull pack2(float lo, float hi) {
    ull r; asm("mov.b64 %0, {%1, %2};" : "=l"(r) : "f"(lo), "f"(hi)); return r;
}
__device__ __forceinline__ void unpack2(ull v, float& lo, float& hi) {
    asm("mov.b64 {%0, %1}, %2;" : "=f"(lo), "=f"(hi) : "l"(v));
}
__device__ __forceinline__ void fma2(ull& a, ull b, ull c) {
    asm("fma.rn.f32x2 %0, %1, %2, %0;" : "+l"(a) : "l"(b), "l"(c));
}

// ---------------------------------------------------------------------------
// cp.async helpers
// ---------------------------------------------------------------------------
__device__ __forceinline__ void cpa4(unsigned int dst, const float* src, bool ok) {
    asm volatile("cp.async.ca.shared.global [%0], [%1], 4, %2;\n"
                 :: "r"(dst), "l"(src), "r"(ok ? 4u : 0u));
}
__device__ __forceinline__ void cpa_commit() {
    asm volatile("cp.async.commit_group;\n");
}
template<int N>
__device__ __forceinline__ void cpa_wait() {
    asm volatile("cp.async.wait_group %0;\n" :: "n"(N));
}

// ---------------------------------------------------------------------------
// Direct 3x3 conv, pad=1, stride=1, NCHW, fp32.
// 256 threads -> 32x32 output tile, 2x2 outputs/thread (x-pair packed f32x2),
// COPB output channels per block, 2-stage cp.async pipeline over Cin.
// ACT: 0=none 1=relu 2=sigmoid; BN: per-channel scale/shift after relu.
// ---------------------------------------------------------------------------
template<int COPB, int ACT, bool BN>
__global__ void __launch_bounds__(256, 2)
conv3x3_k(const float* __restrict__ in, const float* __restrict__ wt,
          const float* __restrict__ bias, float* __restrict__ out,
          int N, int Cin, int Co, int H, int W,
          const float* __restrict__ bnsc, const float* __restrict__ bnsh)
{
    __shared__ __align__(16) float s_in[2][1160];   // 34x34 halo tile
    __shared__ __align__(16) float s_w[2][COPB * 9];

    const int tid = threadIdx.x;
    const int tx = tid & 15;
    const int ty = tid >> 4;
    const int tile_x = blockIdx.x * 32;
    const int tile_y = blockIdx.y * 32;
    const int co_blocks = (Co + COPB - 1) / COPB;
    const int n   = blockIdx.z / co_blocks;
    const int co0 = (blockIdx.z % co_blocks) * COPB;

    const float* inN = in + (size_t)n * Cin * H * W;

    // ---- hoist ci-invariant halo-load addressing ----
    int  h_off[5];
    bool h_ok[5];
#pragma unroll
    for (int k = 0; k < 5; k++) {
        int idx = tid + k * 256;
        h_ok[k] = false; h_off[k] = 0;
        if (idx < 1156) {
            int iy = tile_y - 1 + idx / 34;
            int ix = tile_x - 1 + idx % 34;
            bool ok = (iy >= 0 && iy < H && ix >= 0 && ix < W);
            h_ok[k]  = ok;
            h_off[k] = ok ? iy * W + ix : 0;
        }
    }
    const bool w_ld = (tid < COPB * 9);
    size_t w_base = 0;
    if (w_ld) {
        int j = tid / 9, k = tid - j * 9;
        w_base = ((size_t)(co0 + j) * Cin) * 9 + k;   // + ci*9 per stage
    }

    unsigned int s_in_a[2], s_w_a[2];
    s_in_a[0] = (unsigned int)__cvta_generic_to_shared(&s_in[0][0]);
    s_in_a[1] = (unsigned int)__cvta_generic_to_shared(&s_in[1][0]);
    s_w_a[0]  = (unsigned int)__cvta_generic_to_shared(&s_w[0][0]);
    s_w_a[1]  = (unsigned int)__cvta_generic_to_shared(&s_w[1][0]);

    auto issue_stage = [&](int ci, int s) {
        const float* inC = inN + (size_t)ci * H * W;
#pragma unroll
        for (int k = 0; k < 5; k++) {
            int idx = tid + k * 256;
            if (idx < 1156)
                cpa4(s_in_a[s] + (unsigned int)idx * 4u, inC + h_off[k], h_ok[k]);
        }
        if (w_ld)
            cpa4(s_w_a[s] + (unsigned int)tid * 4u, wt + w_base + (size_t)ci * 9, true);
        cpa_commit();
    };

    ull accp[COPB][2];
#pragma unroll
    for (int j = 0; j < COPB; j++) { accp[j][0] = 0ull; accp[j][1] = 0ull; }

    issue_stage(0, 0);

    for (int ci = 0; ci < Cin; ci++) {
        const int cur = ci & 1;
        if (ci + 1 < Cin) {
            issue_stage(ci + 1, cur ^ 1);
            cpa_wait<1>();
        } else {
            cpa_wait<0>();
        }
        __syncthreads();

        const float* si = s_in[cur];
        const float* sw = s_w[cur];

        // 4 rows x 3 overlapping x-pairs
        ull P[4][3];
#pragma unroll
        for (int dy = 0; dy < 4; dy++) {
            const int base = (2 * ty + dy) * 34 + 2 * tx;
            float2 a = *(const float2*)&si[base];
            float2 b = *(const float2*)&si[base + 2];
            P[dy][0] = pack2(a.x, a.y);
            P[dy][1] = pack2(a.y, b.x);
            P[dy][2] = pack2(b.x, b.y);
        }

#pragma unroll
        for (int j = 0; j < COPB; j++) {
#pragma unroll
            for (int ky = 0; ky < 3; ky++) {
#pragma unroll
                for (int kx = 0; kx < 3; kx++) {
                    float w = sw[j * 9 + ky * 3 + kx];
                    ull wp = pack2(w, w);
                    fma2(accp[j][0], P[ky    ][kx], wp);
                    fma2(accp[j][1], P[ky + 1][kx], wp);
                }
            }
        }
        __syncthreads();
    }

    // ---- epilogue ----
    const int ox = tile_x + 2 * tx;
    const int oy = tile_y + 2 * ty;
    if (ox < W) {
#pragma unroll
        for (int j = 0; j < COPB; j++) {
            int co = co0 + j;
            if (co < Co) {
                float bv = __ldg(&bias[co]);
                float sc = 1.f, sh = 0.f;
                if (BN) { sc = __ldg(&bnsc[co]); sh = __ldg(&bnsh[co]); }
                float v0, v1, v2, v3;
                unpack2(accp[j][0], v0, v1);
                unpack2(accp[j][1], v2, v3);
                v0 += bv; v1 += bv; v2 += bv; v3 += bv;
                if (ACT == 1) {
                    v0 = fmaxf(v0, 0.f); v1 = fmaxf(v1, 0.f);
                    v2 = fmaxf(v2, 0.f); v3 = fmaxf(v3, 0.f);
                }
                if (BN) {
                    v0 = v0 * sc + sh; v1 = v1 * sc + sh;
                    v2 = v2 * sc + sh; v3 = v3 * sc + sh;
                }
                if (ACT == 2) {
                    v0 = 1.f / (1.f + expf(-v0)); v1 = 1.f / (1.f + expf(-v1));
                    v2 = 1.f / (1.f + expf(-v2)); v3 = 1.f / (1.f + expf(-v3));
                }
                float* outC = out + (((size_t)n * Co + co) * H) * W;
                if (oy < H)     *(float2*)&outC[(size_t)oy * W + ox]       = make_float2(v0, v1);
                if (oy + 1 < H) *(float2*)&outC[(size_t)(oy + 1) * W + ox] = make_float2(v2, v3);
            }
        }
    }
}

// ---------------------------------------------------------------------------
// 2x2 max pool, stride 2
// ---------------------------------------------------------------------------
__global__ void maxpool_k(const float* __restrict__ in, float* __restrict__ out,
                          int NC, int H, int W)
{
    int Ho = H >> 1, Wo = W >> 1;
    long total = (long)NC * Ho * Wo;
    for (long i = blockIdx.x * (long)blockDim.x + threadIdx.x; i < total;
         i += (long)gridDim.x * blockDim.x) {
        int xo = (int)(i % Wo);
        int yo = (int)((i / Wo) % Ho);
        long nc = i / ((long)Wo * Ho);
        const float* p = in + (size_t)nc * H * W + (size_t)(2 * yo) * W + 2 * xo;
        out[i] = fmaxf(fmaxf(p[0], p[1]), fmaxf(p[W], p[W + 1]));
    }
}

// ---------------------------------------------------------------------------
// Bilinear 2x upsample, align_corners=True
// ---------------------------------------------------------------------------
__global__ void up2_k(const float* __restrict__ in, float* __restrict__ out,
                      int NC, int H, int W)
{
    int Ho = 2 * H, Wo = 2 * W;
    float sy = (float)(H - 1) / (float)(Ho - 1);
    float sx = (float)(W - 1) / (float)(Wo - 1);
    long total = (long)NC * Ho * Wo;
    for (long i = blockIdx.x * (long)blockDim.x + threadIdx.x; i < total;
         i += (long)gridDim.x * blockDim.x) {
        int xo = (int)(i % Wo);
        int yo = (int)((i / Wo) % Ho);
        long nc = i / ((long)Wo * Ho);
        float ys = yo * sy, xs = xo * sx;
        int y0 = (int)floorf(ys), x0 = (int)floorf(xs);
        int y1 = min(y0 + 1, H - 1), x1 = min(x0 + 1, W - 1);
        float wy = ys - (float)y0, wx = xs - (float)x0;
        const float* p = in + (size_t)nc * H * W;
        float a = p[y0 * W + x0] * (1.f - wy) + p[y1 * W + x0] * wy;
        float b = p[y0 * W + x1] * (1.f - wy) + p[y1 * W + x1] * wy;
        out[i] = a * (1.f - wx) + b * wx;
    }
}

// ---------------------------------------------------------------------------
// Block attention, collapsed:
//   t = fold of 16 blocks; w16[m,n] = <block(m,n), t>/676; y = x * w16[blk]
// ---------------------------------------------------------------------------
__global__ void attn_t_k(const float* __restrict__ x, float* __restrict__ t)
{
    const int total = 4 * 128 * 26 * 26;
    for (int i = blockIdx.x * blockDim.x + threadIdx.x; i < total;
         i += gridDim.x * blockDim.x) {
        int w  = i % 26;
        int h  = (i / 26) % 26;
        int bc = i / 676;
        const float* p = x + (size_t)bc * 104 * 104;
        float s = 0.f;
#pragma unroll
        for (int k = 0; k < 4; k++)
#pragma unroll
            for (int l = 0; l < 4; l++)
                s += p[(k * 26 + h) * 104 + l * 26 + w];
        t[i] = s;
    }
}

__global__ void attn_w_k(const float* __restrict__ x, const float* __restrict__ t,
                         float* __restrict__ w16)
{
    const int mn = blockIdx.x;
    const int m = mn >> 2, nn = mn & 3;
    const int total = 4 * 128 * 26 * 26;
    float s = 0.f;
    for (int i = threadIdx.x; i < total; i += blockDim.x) {
        int w  = i % 26;
        int h  = (i / 26) % 26;
        int bc = i / 676;
        s += x[(size_t)bc * 104 * 104 + (m * 26 + h) * 104 + nn * 26 + w] * t[i];
    }
    __shared__ float red[1024];
    red[threadIdx.x] = s;
    __syncthreads();
    for (int st = blockDim.x >> 1; st > 0; st >>= 1) {
        if (threadIdx.x < st) red[threadIdx.x] += red[threadIdx.x + st];
        __syncthreads();
    }
    if (threadIdx.x == 0) w16[mn] = red[0] * (1.f / 676.f);
}

__global__ void attn_scale_k(float* __restrict__ x, const float* __restrict__ w16)
{
    const long total = 4L * 128 * 104 * 104;
    for (long i = blockIdx.x * (long)blockDim.x + threadIdx.x; i < total;
         i += (long)gridDim.x * blockDim.x) {
        int j  = (int)(i % 104);
        int ii = (int)((i / 104) % 104);
        x[i] *= w16[(ii / 26) * 4 + (j / 26)];
    }
}

// ---------------------------------------------------------------------------
// Fold BN (inference) into per-channel scale/shift.
// ---------------------------------------------------------------------------
__global__ void bn_prep_k(const float* __restrict__ g, const float* __restrict__ b,
                          const float* __restrict__ m, const float* __restrict__ v,
                          float* __restrict__ sc, float* __restrict__ sh, int C)
{
    int c = blockIdx.x * blockDim.x + threadIdx.x;
    if (c < C) {
        float s = g[c] / sqrtf(v[c] + 1e-5f);
        sc[c] = s;
        sh[c] = b[c] - m[c] * s;
    }
}

// ---------------------------------------------------------------------------
// Host orchestration (graph-capturable: kernel launches only, default stream)
// ---------------------------------------------------------------------------
static inline dim3 conv_grid(int W, int H, int N, int Co, int copb)
{
    return dim3((W + 31) / 32, (H + 31) / 32, N * ((Co + copb - 1) / copb));
}

extern "C" void kernel_launch(void* const* d_in, const int* in_sizes, int n_in,
                              void* d_out, int out_size)
{
    (void)in_sizes; (void)n_in; (void)out_size;
    const float* x    = (const float*)d_in[0];
    const float* w1   = (const float*)d_in[1];
    const float* b1   = (const float*)d_in[2];
    const float* w2   = (const float*)d_in[3];
    const float* b2   = (const float*)d_in[4];
    const float* w3   = (const float*)d_in[5];
    const float* b3   = (const float*)d_in[6];
    const float* w4   = (const float*)d_in[7];
    const float* b4   = (const float*)d_in[8];
    const float* dw1  = (const float*)d_in[9];
    const float* db1  = (const float*)d_in[10];
    const float* dw2  = (const float*)d_in[11];
    const float* db2  = (const float*)d_in[12];
    const float* dw3  = (const float*)d_in[13];
    const float* db3  = (const float*)d_in[14];
    const float* dw4  = (const float*)d_in[15];
    const float* db4  = (const float*)d_in[16];
    const float* dw5  = (const float*)d_in[17];
    const float* db5  = (const float*)d_in[18];
    const float* bn2g = (const float*)d_in[19];
    const float* bn2b = (const float*)d_in[20];
    const float* bn2m = (const float*)d_in[21];
    const float* bn2v = (const float*)d_in[22];
    const float* bn4g = (const float*)d_in[23];
    const float* bn4b = (const float*)d_in[24];
    const float* bn4m = (const float*)d_in[25];
    const float* bn4v = (const float*)d_in[26];
    float* out = (float*)d_out;

    float *buf0, *buf1, *tb, *w16, *bnsc, *bnsh;
    cudaGetSymbolAddress((void**)&buf0, g_buf0);
    cudaGetSymbolAddress((void**)&buf1, g_buf1);
    cudaGetSymbolAddress((void**)&tb,   g_t);
    cudaGetSymbolAddress((void**)&w16,  g_w16);
    cudaGetSymbolAddress((void**)&bnsc, g_bnsc);
    cudaGetSymbolAddress((void**)&bnsh, g_bnsh);

    // Encoder
    conv3x3_k<8,1,false><<<conv_grid(416, 416, 4, 64, 8), 256>>>(x,    w1, b1, buf0, 4, 3,   64, 416, 416, nullptr, nullptr);
    conv3x3_k<8,1,false><<<conv_grid(416, 416, 4, 64, 8), 256>>>(buf0, w2, b2, buf1, 4, 64,  64, 416, 416, nullptr, nullptr);
    maxpool_k<<<4096, 256>>>(buf1, buf0, 4 * 64, 416, 416);
    conv3x3_k<8,1,false><<<conv_grid(208, 208, 4, 128, 8), 256>>>(buf0, w3, b3, buf1, 4, 64,  128, 208, 208, nullptr, nullptr);
    conv3x3_k<8,1,false><<<conv_grid(208, 208, 4, 128, 8), 256>>>(buf1, w4, b4, buf0, 4, 128, 128, 208, 208, nullptr, nullptr);
    maxpool_k<<<2048, 256>>>(buf0, buf1, 4 * 128, 208, 208);

    // Block attention x2 (in-place on buf1)
    attn_t_k<<<1352, 256>>>(buf1, tb);
    attn_w_k<<<16, 1024>>>(buf1, tb, w16);
    attn_scale_k<<<2048, 256>>>(buf1, w16);
    attn_t_k<<<1352, 256>>>(buf1, tb);
    attn_w_k<<<16, 1024>>>(buf1, tb, w16);
    attn_scale_k<<<2048, 256>>>(buf1, w16);

    // Decoder
    conv3x3_k<8,1,false><<<conv_grid(104, 104, 4, 128, 8), 256>>>(buf1, dw1, db1, buf0, 4, 128, 128, 104, 104, nullptr, nullptr);
    bn_prep_k<<<1, 128>>>(bn2g, bn2b, bn2m, bn2v, bnsc, bnsh, 128);
    conv3x3_k<8,1,true ><<<conv_grid(104, 104, 4, 128, 8), 256>>>(buf0, dw2, db2, buf1, 4, 128, 128, 104, 104, bnsc, bnsh);
    up2_k<<<2048, 256>>>(buf1, buf0, 4 * 128, 104, 104);
    conv3x3_k<8,1,false><<<conv_grid(208, 208, 4, 64, 8), 256>>>(buf0, dw3, db3, buf1, 4, 128, 64, 208, 208, nullptr, nullptr);
    bn_prep_k<<<1, 64>>>(bn4g, bn4b, bn4m, bn4v, bnsc, bnsh, 64);
    conv3x3_k<8,1,true ><<<conv_grid(208, 208, 4, 64, 8), 256>>>(buf1, dw4, db4, buf0, 4, 64, 64, 208, 208, bnsc, bnsh);
    up2_k<<<4096, 256>>>(buf0, buf1, 4 * 64, 208, 208);
    conv3x3_k<2,2,false><<<conv_grid(416, 416, 4, 2, 2), 256>>>(buf1, dw5, db5, out, 4, 64, 2, 416, 416, nullptr, nullptr);
}